// round 4
// baseline (speedup 1.0000x reference)
#include <cuda_runtime.h>
#include <math.h>

// SE(3) exp + point transform (single kernel).
// out[bt,n,:] = R(dofs[bt]) * X[bt,n,:] + t(dofs[bt])
// X_v: [B,T,N,3] f32, dofs: [B,T,6] f32, out: [B,T,N,3] f32. B=64,T=28,N=4096.
//
// Every thread computes R,t redundantly (no smem, no barrier); the 6 float4
// data loads are independent of that math, so they issue first and the
// sincos/divide chain executes under the memory latency.

#define THREADS 256
#define PTS_PER_THREAD 8   // 8 points = 24 floats = 6 float4

__global__ void __launch_bounds__(THREADS)
se3_transform_kernel(const float* __restrict__ X,
                     const float* __restrict__ dofs,
                     float* __restrict__ out,
                     int N)
{
    const int bt = blockIdx.y;

    const int ptBase = (blockIdx.x * THREADS + threadIdx.x) * PTS_PER_THREAD;
    if (ptBase >= N) return;

    const size_t base = (size_t)bt * (size_t)N * 3 + (size_t)ptBase * 3;
    const float4* __restrict__ src = reinterpret_cast<const float4*>(X + base);
    float4* __restrict__ dst = reinterpret_cast<float4*>(out + base);

    // ---- issue all memory reads up front (dofs broadcast + 6 data float4s) ----
    const float* d = dofs + bt * 6;
    const float tx = __ldg(&d[0]), ty = __ldg(&d[1]), tz = __ldg(&d[2]);
    const float wx = __ldg(&d[3]), wy = __ldg(&d[4]), wz = __ldg(&d[5]);

    const float4 va = __ldcs(&src[0]);
    const float4 vb = __ldcs(&src[1]);
    const float4 vc = __ldcs(&src[2]);
    const float4 vd = __ldcs(&src[3]);
    const float4 ve = __ldcs(&src[4]);
    const float4 vf = __ldcs(&src[5]);

    // ---- SE(3) exp (runs under load latency; no barrier, no smem) ----
    const float nrm   = wx*wx + wy*wy + wz*wz;
    const float th2c  = fmaxf(nrm, 1.0e-4f);   // clip BEFORE sqrt (matches ref)
    const float theta = sqrtf(th2c);
    float st, ct;
    sincosf(theta, &st, &ct);
    const float inv_t  = 1.0f / theta;
    const float inv_t2 = inv_t * inv_t;
    const float f1 = st * inv_t;
    const float f2 = (1.0f - ct) * inv_t2;
    const float f3 = (theta - st) * inv_t2 * inv_t;

    // H2 = H@H = w w^T - (w.w) I  (raw nrm, matches ref)
    const float h2xx = wx*wx - nrm, h2yy = wy*wy - nrm, h2zz = wz*wz - nrm;
    const float h2xy = wx*wy, h2xz = wx*wz, h2yz = wy*wz;

    const float r00 = 1.0f + f2*h2xx;
    const float r01 = -f1*wz + f2*h2xy;
    const float r02 =  f1*wy + f2*h2xz;
    const float r10 =  f1*wz + f2*h2xy;
    const float r11 = 1.0f + f2*h2yy;
    const float r12 = -f1*wx + f2*h2yz;
    const float r20 = -f1*wy + f2*h2xz;
    const float r21 =  f1*wx + f2*h2yz;
    const float r22 = 1.0f + f2*h2zz;

    const float v00 = 1.0f + f3*h2xx;
    const float v01 = -f2*wz + f3*h2xy;
    const float v02 =  f2*wy + f3*h2xz;
    const float v10 =  f2*wz + f3*h2xy;
    const float v11 = 1.0f + f3*h2yy;
    const float v12 = -f2*wx + f3*h2yz;
    const float v20 = -f2*wy + f3*h2xz;
    const float v21 =  f2*wx + f3*h2yz;
    const float v22 = 1.0f + f3*h2zz;

    const float t0 = v00*tx + v01*ty + v02*tz;
    const float t1 = v10*tx + v11*ty + v12*tz;
    const float t2 = v20*tx + v21*ty + v22*tz;

    // ---- transform 8 points (24 floats packed in va..vf) ----
#define XFX(px, py, pz) fmaf(r00, (px), fmaf(r01, (py), fmaf(r02, (pz), t0)))
#define XFY(px, py, pz) fmaf(r10, (px), fmaf(r11, (py), fmaf(r12, (pz), t1)))
#define XFZ(px, py, pz) fmaf(r20, (px), fmaf(r21, (py), fmaf(r22, (pz), t2)))

    // group 0: points 0..3 in va,vb,vc
    const float o0x = XFX(va.x, va.y, va.z), o0y = XFY(va.x, va.y, va.z), o0z = XFZ(va.x, va.y, va.z);
    const float o1x = XFX(va.w, vb.x, vb.y), o1y = XFY(va.w, vb.x, vb.y), o1z = XFZ(va.w, vb.x, vb.y);
    const float o2x = XFX(vb.z, vb.w, vc.x), o2y = XFY(vb.z, vb.w, vc.x), o2z = XFZ(vb.z, vb.w, vc.x);
    const float o3x = XFX(vc.y, vc.z, vc.w), o3y = XFY(vc.y, vc.z, vc.w), o3z = XFZ(vc.y, vc.z, vc.w);

    __stcs(&dst[0], make_float4(o0x, o0y, o0z, o1x));
    __stcs(&dst[1], make_float4(o1y, o1z, o2x, o2y));
    __stcs(&dst[2], make_float4(o2z, o3x, o3y, o3z));

    // group 1: points 4..7 in vd,ve,vf
    const float o4x = XFX(vd.x, vd.y, vd.z), o4y = XFY(vd.x, vd.y, vd.z), o4z = XFZ(vd.x, vd.y, vd.z);
    const float o5x = XFX(vd.w, ve.x, ve.y), o5y = XFY(vd.w, ve.x, ve.y), o5z = XFZ(vd.w, ve.x, ve.y);
    const float o6x = XFX(ve.z, ve.w, vf.x), o6y = XFY(ve.z, ve.w, vf.x), o6z = XFZ(ve.z, ve.w, vf.x);
    const float o7x = XFX(vf.y, vf.z, vf.w), o7y = XFY(vf.y, vf.z, vf.w), o7z = XFZ(vf.y, vf.z, vf.w);

    __stcs(&dst[3], make_float4(o4x, o4y, o4z, o5x));
    __stcs(&dst[4], make_float4(o5y, o5z, o6x, o6y));
    __stcs(&dst[5], make_float4(o6z, o7x, o7y, o7z));

#undef XFX
#undef XFY
#undef XFZ
}

extern "C" void kernel_launch(void* const* d_in, const int* in_sizes, int n_in,
                              void* d_out, int out_size)
{
    const float* X    = (const float*)d_in[0];   // [B,T,N,3]
    const float* dofs = (const float*)d_in[1];   // [B,T,6]

    const int nBT = in_sizes[1] / 6;             // 1792
    const int N   = (in_sizes[0] / nBT) / 3;     // 4096

    const int ptsPerBlock = THREADS * PTS_PER_THREAD;        // 2048
    const int blocksX = (N + ptsPerBlock - 1) / ptsPerBlock; // 2

    dim3 grid(blocksX, nBT);
    se3_transform_kernel<<<grid, THREADS>>>(X, dofs, (float*)d_out, N);
}